// round 2
// baseline (speedup 1.0000x reference)
#include <cuda_runtime.h>
#include <cuda_fp16.h>
#include <cstdint>

#define NPIX   100352     // 32*56*56
#define IMGPIX 3136       // 56*56
#define HH     56
#define WWD    56
#define CCH    256
#define KTOT   2304       // 9*256
#define NKSTEP 72         // 2304/32

// ---------------- scratch (device globals; no allocation) ----------------
__device__ __half g_Q[(size_t)NPIX * CCH];   // quantized input, NHWC fp16
__device__ __half g_A[(size_t)NPIX * CCH];   // conv1 output (quantized), NHWC fp16
__device__ __half g_W1[KTOT * CCH];          // sign(w1), [k][co]
__device__ __half g_W2[KTOT * CCH];          // sign(w2), [k][co]

// ---------------- helpers ----------------
__device__ __forceinline__ float quantf(float x) {
    // round to nearest multiple of 1/128, ties -> upper (matches reference exactly:
    // all intermediate ops are exact in fp32)
    float s  = floorf(x * 128.0f);
    float t1 = s * 0.0078125f;
    float r  = x - t1;
    return (r < 0.0078125f - r) ? t1 : (t1 + 0.0078125f);
}

__device__ __forceinline__ uint32_t smaddr(const void* p) {
    return (uint32_t)__cvta_generic_to_shared(p);
}

__device__ __forceinline__ void cp16(uint32_t dst, const void* src, int srcbytes) {
    asm volatile("cp.async.ca.shared.global [%0], [%1], 16, %2;\n"
                 :: "r"(dst), "l"(src), "r"(srcbytes) : "memory");
}

// ---------------- prep: quantize x (NCHW f32) -> g_Q (NHWC fp16) ----------------
__global__ void __launch_bounds__(256)
prep_x_kernel(const float* __restrict__ x, __half* __restrict__ q) {
    __shared__ __half tile[64][65];
    const int p0 = blockIdx.x * 64;          // 64 | 3136 -> tile never crosses an image
    const int c0 = blockIdx.y * 64;
    const int n   = p0 / IMGPIX;
    const int rem = p0 % IMGPIX;
    const int t = threadIdx.x;
    #pragma unroll
    for (int i = 0; i < 16; ++i) {
        int c = i * 4 + (t >> 6);
        int p = t & 63;
        float v = x[(n * 256 + c0 + c) * IMGPIX + rem + p];
        tile[c][p] = __float2half_rn(quantf(v));
    }
    __syncthreads();
    #pragma unroll
    for (int i = 0; i < 16; ++i) {
        int p = i * 4 + (t >> 6);
        int c = t & 63;
        q[(p0 + p) * 256 + c0 + c] = tile[c][p];
    }
}

// ---------------- prep: sign(w) OIHW -> [k = tap*256+ci][co] fp16 ----------------
__global__ void __launch_bounds__(256)
prep_w_kernel(const float* __restrict__ w1, const float* __restrict__ w2,
              __half* __restrict__ o1, __half* __restrict__ o2) {
    int j = blockIdx.x * blockDim.x + threadIdx.x;
    const int NW = KTOT * CCH;
    if (j >= 2 * NW) return;
    const float* w = (j < NW) ? w1 : w2;
    __half* o      = (j < NW) ? o1 : o2;
    int i = (j < NW) ? j : j - NW;
    int co  = i & 255;
    int k   = i >> 8;        // 0..2303
    int ci  = k & 255;
    int tap = k >> 8;        // ky*3+kx
    float v = w[((co << 8) + ci) * 9 + tap];
    o[i] = __float2half(v >= 0.0f ? 1.0f : -1.0f);
}

// ---------------- implicit-GEMM conv: 128 pixels x 128 co, K=2304 ----------------
// MODE 0: epilogue = BN1 -> clip -> quantize -> NHWC fp16 (g_A)
// MODE 1: epilogue = +residual -> BN2 -> clip -> NCHW fp32 (d_out)
template<int MODE>
__global__ void __launch_bounds__(256)
conv_kernel(const __half* __restrict__ Ain, const __half* __restrict__ Wb,
            const float* __restrict__ gg, const float* __restrict__ bbv,
            const float* __restrict__ mmn, const float* __restrict__ vvr,
            const float* __restrict__ resid, void* __restrict__ outp)
{
    extern __shared__ char dsm[];
    __half* As = (__half*)dsm;               // [2][128][40]  (pad 40 -> conflict-free ldmatrix)
    __half* Bs = (__half*)(dsm + 20480);     // [2][32][136]  (pad 136)
    __shared__ float s_sc[128], s_sh[128];

    const int tid  = threadIdx.x;
    const int lane = tid & 31;
    const int warp = tid >> 5;
    const int wm   = warp >> 2;   // 0..1  (64-row slab)
    const int wn   = warp & 3;    // 0..3  (32-col slab)
    const int p0   = blockIdx.x * 128;
    const int co0  = blockIdx.y * 128;

    if (tid < 128) {
        int c = co0 + tid;
        float inv = gg[c] * __frsqrt_rn(vvr[c] + 1e-5f);
        s_sc[tid] = inv;
        s_sh[tid] = bbv[c] - mmn[c] * inv;
    }

    // A-load assignment: rows rA and rA+64, 16B chunk (tid&3)*8 halfs
    const int rA  = tid >> 2;
    const int ciA = (tid & 3) * 8;
    const int pA0 = p0 + rA, pA1 = pA0 + 64;
    const int n0 = pA0 / IMGPIX, q0 = pA0 % IMGPIX;
    const int y0 = q0 / WWD,     x0g = q0 % WWD;
    const int n1 = pA1 / IMGPIX, q1 = pA1 % IMGPIX;
    const int y1 = q1 / WWD,     x1g = q1 % WWD;
    // B-load assignment: k rows kB and kB+16, 16B chunk (tid&15)*8
    const int kB  = tid >> 4;
    const int coB = (tid & 15) * 8;

    float acc[4][4][4];
    #pragma unroll
    for (int a = 0; a < 4; ++a)
        #pragma unroll
        for (int b = 0; b < 4; ++b)
            #pragma unroll
            for (int c = 0; c < 4; ++c) acc[a][b][c] = 0.0f;

    auto issue = [&](int kk, int buf) {
        const int k0  = kk * 32;
        const int tap = k0 >> 8;         // constant per 8 k-steps: (ky,kx)
        const int ci0 = (k0 & 255) + ciA;
        const int dy  = tap / 3 - 1;
        const int dx  = tap - (tap / 3) * 3 - 1;
        {
            int yy = y0 + dy, xx = x0g + dx;
            bool ok = ((unsigned)yy < HH) && ((unsigned)xx < WWD);
            const __half* src = Ain + ((n0 * IMGPIX + yy * WWD + xx) * 256 + ci0);
            cp16(smaddr(As + (buf * 128 + rA) * 40 + ciA),
                 ok ? (const void*)src : (const void*)Ain, ok ? 16 : 0);
        }
        {
            int yy = y1 + dy, xx = x1g + dx;
            bool ok = ((unsigned)yy < HH) && ((unsigned)xx < WWD);
            const __half* src = Ain + ((n1 * IMGPIX + yy * WWD + xx) * 256 + ci0);
            cp16(smaddr(As + (buf * 128 + rA + 64) * 40 + ciA),
                 ok ? (const void*)src : (const void*)Ain, ok ? 16 : 0);
        }
        cp16(smaddr(Bs + (buf * 32 + kB) * 136 + coB),
             Wb + (k0 + kB) * 256 + co0 + coB, 16);
        cp16(smaddr(Bs + (buf * 32 + kB + 16) * 136 + coB),
             Wb + (k0 + kB + 16) * 256 + co0 + coB, 16);
    };

    issue(0, 0);
    asm volatile("cp.async.commit_group;\n" ::: "memory");

    #pragma unroll 1
    for (int kk = 0; kk < NKSTEP; ++kk) {
        const int buf = kk & 1;
        if (kk + 1 < NKSTEP) {
            issue(kk + 1, buf ^ 1);
            asm volatile("cp.async.commit_group;\n" ::: "memory");
            asm volatile("cp.async.wait_group 1;\n" ::: "memory");
        } else {
            asm volatile("cp.async.wait_group 0;\n" ::: "memory");
        }
        __syncthreads();

        const __half* Ab = As + buf * 128 * 40;
        const __half* Bb = Bs + buf * 32 * 136;
        #pragma unroll
        for (int ks = 0; ks < 2; ++ks) {
            const int kb = ks * 16;
            uint32_t af[4][4], bf[2][4];
            #pragma unroll
            for (int mi = 0; mi < 4; ++mi) {
                const int row = wm * 64 + mi * 16 + (lane & 15);
                const int col = kb + (lane >> 4) * 8;
                uint32_t a = smaddr(Ab + row * 40 + col);
                asm volatile("ldmatrix.sync.aligned.m8n8.x4.shared.b16 {%0,%1,%2,%3}, [%4];\n"
                             : "=r"(af[mi][0]), "=r"(af[mi][1]), "=r"(af[mi][2]), "=r"(af[mi][3])
                             : "r"(a));
            }
            #pragma unroll
            for (int ni = 0; ni < 2; ++ni) {
                const int krow = kb + (lane & 15);
                const int col  = wn * 32 + ni * 16 + (lane >> 4) * 8;
                uint32_t a = smaddr(Bb + krow * 136 + col);
                asm volatile("ldmatrix.sync.aligned.m8n8.x4.trans.shared.b16 {%0,%1,%2,%3}, [%4];\n"
                             : "=r"(bf[ni][0]), "=r"(bf[ni][1]), "=r"(bf[ni][2]), "=r"(bf[ni][3])
                             : "r"(a));
            }
            #pragma unroll
            for (int mi = 0; mi < 4; ++mi)
                #pragma unroll
                for (int nj = 0; nj < 4; ++nj) {
                    float* d = acc[mi][nj];
                    asm volatile("mma.sync.aligned.m16n8k16.row.col.f32.f16.f16.f32 "
                                 "{%0,%1,%2,%3}, {%4,%5,%6,%7}, {%8,%9}, {%0,%1,%2,%3};\n"
                                 : "+f"(d[0]), "+f"(d[1]), "+f"(d[2]), "+f"(d[3])
                                 : "r"(af[mi][0]), "r"(af[mi][1]), "r"(af[mi][2]), "r"(af[mi][3]),
                                   "r"(bf[nj >> 1][(nj & 1) * 2]), "r"(bf[nj >> 1][(nj & 1) * 2 + 1]));
                }
        }
        __syncthreads();
    }

    const int g4 = lane >> 2, t4 = lane & 3;

    if (MODE == 0) {
        // stage as half2 [128 pixels][65 co-pairs], then coalesced NHWC stores
        uint32_t* stg = (uint32_t*)dsm;
        #pragma unroll
        for (int mi = 0; mi < 4; ++mi)
            #pragma unroll
            for (int nj = 0; nj < 4; ++nj) {
                int row = wm * 64 + mi * 16 + g4;
                int col = wn * 32 + nj * 8 + t4 * 2;
                float v0 = quantf(fminf(1.f, fmaxf(-1.f, fmaf(acc[mi][nj][0], s_sc[col],     s_sh[col]))));
                float v1 = quantf(fminf(1.f, fmaxf(-1.f, fmaf(acc[mi][nj][1], s_sc[col + 1], s_sh[col + 1]))));
                float v2 = quantf(fminf(1.f, fmaxf(-1.f, fmaf(acc[mi][nj][2], s_sc[col],     s_sh[col]))));
                float v3 = quantf(fminf(1.f, fmaxf(-1.f, fmaf(acc[mi][nj][3], s_sc[col + 1], s_sh[col + 1]))));
                __half2 h01 = __floats2half2_rn(v0, v1);
                __half2 h23 = __floats2half2_rn(v2, v3);
                stg[row * 65 + (col >> 1)]       = *(uint32_t*)&h01;
                stg[(row + 8) * 65 + (col >> 1)] = *(uint32_t*)&h23;
            }
        __syncthreads();
        uint32_t* outH = (uint32_t*)outp;
        #pragma unroll
        for (int j = tid; j < 128 * 64; j += 256) {
            int row = j >> 6, cc = j & 63;
            outH[(p0 + row) * 128 + (co0 >> 1) + cc] = stg[row * 65 + cc];
        }
    } else {
        // stage transposed [128 co][129 pixels] fp32, then coalesced NCHW out + residual
        float* stg = (float*)dsm;
        #pragma unroll
        for (int mi = 0; mi < 4; ++mi)
            #pragma unroll
            for (int nj = 0; nj < 4; ++nj) {
                int row = wm * 64 + mi * 16 + g4;
                int col = wn * 32 + nj * 8 + t4 * 2;
                stg[col * 129 + row]             = acc[mi][nj][0];
                stg[(col + 1) * 129 + row]       = acc[mi][nj][1];
                stg[col * 129 + row + 8]         = acc[mi][nj][2];
                stg[(col + 1) * 129 + row + 8]   = acc[mi][nj][3];
            }
        __syncthreads();
        float* outF = (float*)outp;
        #pragma unroll
        for (int j = tid; j < 128 * 128; j += 256) {
            int cc = j >> 7, pp = j & 127;
            int p = p0 + pp;
            int n = p / IMGPIX, rem = p - n * IMGPIX;
            int addr = (n * 256 + co0 + cc) * IMGPIX + rem;
            float v = stg[cc * 129 + pp] + resid[addr];
            v = fmaf(v, s_sc[cc], s_sh[cc]);
            v = fminf(1.f, fmaxf(-1.f, v));
            outF[addr] = v;
        }
    }
}

// ---------------- launch ----------------
extern "C" void kernel_launch(void* const* d_in, const int* in_sizes, int n_in,
                              void* d_out, int out_size) {
    (void)in_sizes; (void)n_in; (void)out_size;
    const float* x  = (const float*)d_in[0];
    const float* w1 = (const float*)d_in[1];
    const float* w2 = (const float*)d_in[2];
    const float* g1 = (const float*)d_in[3];
    const float* b1 = (const float*)d_in[4];
    const float* m1 = (const float*)d_in[5];
    const float* v1 = (const float*)d_in[6];
    const float* g2 = (const float*)d_in[7];
    const float* b2 = (const float*)d_in[8];
    const float* m2 = (const float*)d_in[9];
    const float* v2 = (const float*)d_in[10];

    __half *Q, *A, *W1, *W2;
    cudaGetSymbolAddress((void**)&Q,  g_Q);
    cudaGetSymbolAddress((void**)&A,  g_A);
    cudaGetSymbolAddress((void**)&W1, g_W1);
    cudaGetSymbolAddress((void**)&W2, g_W2);

    const int SMEM0 = 40960;           // pipeline 37888 (>= stage 33280)
    const int SMEM1 = 128 * 129 * 4;   // 66048 fp32 stage
    cudaFuncSetAttribute(conv_kernel<0>, cudaFuncAttributeMaxDynamicSharedMemorySize, SMEM0);
    cudaFuncSetAttribute(conv_kernel<1>, cudaFuncAttributeMaxDynamicSharedMemorySize, SMEM1);

    prep_w_kernel<<<(2 * KTOT * CCH + 255) / 256, 256>>>(w1, w2, W1, W2);
    prep_x_kernel<<<dim3(NPIX / 64, 4), 256>>>(x, Q);
    conv_kernel<0><<<dim3(NPIX / 128, 2), 256, SMEM0>>>(Q, W1, g1, b1, m1, v1, nullptr, (void*)A);
    conv_kernel<1><<<dim3(NPIX / 128, 2), 256, SMEM1>>>(A, W2, g2, b2, m2, v2, x, d_out);
}